// round 14
// baseline (speedup 1.0000x reference)
#include <cuda_runtime.h>
#include <cstdint>

#define B_ROWS 4096
#define N_LEN  8192
#define M_FFT  4096
#define THREADS 512
#define N_PAIRS (B_ROWS / 2)     // 2048 row-pairs
#define GRID_CTAS 296            // 148 SMs x 2 CTAs/SM, persistent

#define MIN_IDX 273           // argmin |f - 40/60|  (f[i] = i*5/2048, exact fp32)
#define MAX_IDX 1707          // argmin |f - 250/60|  (band = [273, 1707) )
#define DF 0.00244140625f     // 10/4096, exact fp32

// Twiddle table: T[p] = exp(-i*pi*p/4096), p in [0,1028); padded to 1032.
#define TAB_N    1032
#define TAB_BYTES (TAB_N * 8)           // 8256

// smem layout (bytes from dynamic base)
#define ZA_OFF   0
#define ZB_OFF   32768
#define T_OFF    65536
#define MBAR_OFF (T_OFF + TAB_BYTES)    // 73792
#define RED_OFF  (MBAR_OFF + 16)        // 73808 (60 floats scratch)
#define SMEM_TOTAL (RED_OFF + 256)      // 74064

__device__ float g_losses[B_ROWS];
__device__ __align__(16) float2 g_tab[TAB_N];
__device__ unsigned int g_ctr = 0;      // last-CTA counter (self-resetting)

__global__ void twiddle_init_kernel()
{
    int p = blockIdx.x * blockDim.x + threadIdx.x;
    if (p < TAB_N) {
        float s, c;
        sincospif(-(float)p * (1.0f / 4096.0f), &s, &c);
        g_tab[p] = make_float2(c, s);
    }
}

__device__ __forceinline__ uint32_t smem_u32(const void* p)
{
    uint32_t a;
    asm("{ .reg .u64 t; cvta.to.shared.u64 t, %1; cvt.u32.u64 %0, t; }"
        : "=r"(a) : "l"(p));
    return a;
}

// GF(2)-linear swizzle on c64 indices (conflict-free for all stage
// patterns; validated R5-R13, rel_err 0).
__host__ __device__ constexpr int Sc(int i)
{
    return i ^ ((i >> 6) & 1) ^ ((i >> 5) & 0xC) ^ ((i >> 8) & 0xE);
}

// cos(pi*m/32) and sin(pi*m/32) literals, m in [0, 49] (stage<8> twiddles).
__device__ __constant__ const float C64c[50] = {
 1.0f, 0.99518472667219693f, 0.98078528040323044f, 0.95694033573220886f,
 0.92387953251128676f, 0.88192126434835503f, 0.83146961230254524f,
 0.77301045336273696f, 0.70710678118654752f, 0.63439328416364549f,
 0.55557023301960222f, 0.47139673682599764f, 0.38268343236508977f,
 0.29028467725446233f, 0.19509032201612827f, 0.09801714032956060f,
 0.0f, -0.09801714032956060f, -0.19509032201612827f, -0.29028467725446233f,
 -0.38268343236508977f, -0.47139673682599764f, -0.55557023301960222f,
 -0.63439328416364549f, -0.70710678118654752f, -0.77301045336273696f,
 -0.83146961230254524f, -0.88192126434835503f, -0.92387953251128676f,
 -0.95694033573220886f, -0.98078528040323044f, -0.99518472667219693f,
 -1.0f, -0.99518472667219693f, -0.98078528040323044f, -0.95694033573220886f,
 -0.92387953251128676f, -0.88192126434835503f, -0.83146961230254524f,
 -0.77301045336273696f, -0.70710678118654752f, -0.63439328416364549f,
 -0.55557023301960222f, -0.47139673682599764f, -0.38268343236508977f,
 -0.29028467725446233f, -0.19509032201612827f, -0.09801714032956060f,
 0.0f, 0.09801714032956060f };
__device__ __constant__ const float S64c[50] = {
 0.0f, 0.09801714032956060f, 0.19509032201612827f, 0.29028467725446233f,
 0.38268343236508977f, 0.47139673682599764f, 0.55557023301960222f,
 0.63439328416364549f, 0.70710678118654752f, 0.77301045336273696f,
 0.83146961230254524f, 0.88192126434835503f, 0.92387953251128676f,
 0.95694033573220886f, 0.98078528040323044f, 0.99518472667219693f,
 1.0f, 0.99518472667219693f, 0.98078528040323044f, 0.95694033573220886f,
 0.92387953251128676f, 0.88192126434835503f, 0.83146961230254524f,
 0.77301045336273696f, 0.70710678118654752f, 0.63439328416364549f,
 0.55557023301960222f, 0.47139673682599764f, 0.38268343236508977f,
 0.29028467725446233f, 0.19509032201612827f, 0.09801714032956060f,
 0.0f, -0.09801714032956060f, -0.19509032201612827f, -0.29028467725446233f,
 -0.38268343236508977f, -0.47139673682599764f, -0.55557023301960222f,
 -0.63439328416364549f, -0.70710678118654752f, -0.77301045336273696f,
 -0.83146961230254524f, -0.88192126434835503f, -0.92387953251128676f,
 -0.95694033573220886f, -0.98078528040323044f, -0.99518472667219693f,
 -1.0f, -0.99518472667219693f };

#define C64L(m) (C64c[m])
#define S64L(m) (S64c[m])

// ---------- packed f32x2 complex helpers ----------
typedef unsigned long long c64;      // (real, imag) packed as 2 x f32

__device__ __forceinline__ c64 pk(float lo, float hi)
{
    c64 r;
    asm("mov.b64 %0, {%1, %2};" : "=l"(r) : "f"(lo), "f"(hi));
    return r;
}
__device__ __forceinline__ float lof(c64 a)
{
    float f;
    asm("{ .reg .f32 h; mov.b64 {%0, h}, %1; }" : "=f"(f) : "l"(a));
    return f;
}
__device__ __forceinline__ float hif(c64 a)
{
    float f;
    asm("{ .reg .f32 l; mov.b64 {l, %0}, %1; }" : "=f"(f) : "l"(a));
    return f;
}
__device__ __forceinline__ c64 addc(c64 a, c64 b)
{
    c64 r;
    asm("add.rn.f32x2 %0, %1, %2;" : "=l"(r) : "l"(a), "l"(b));
    return r;
}
__device__ __forceinline__ c64 subc(c64 a, c64 b, c64 NEG1)
{
    c64 r;
    asm("fma.rn.f32x2 %0, %1, %2, %3;" : "=l"(r) : "l"(b), "l"(NEG1), "l"(a));
    return r;
}
__device__ __forceinline__ c64 sclc(c64 a, c64 s)
{
    c64 r;
    asm("mul.rn.f32x2 %0, %1, %2;" : "=l"(r) : "l"(a), "l"(s));
    return r;
}
// multiply by -i: (r, i) -> (i, -r)
__device__ __forceinline__ c64 mni(c64 a)
{
    return pk(hif(a), -lof(a));
}
// scalar cmul producing packed result: v * (wr + i*wi)
__device__ __forceinline__ c64 cmulp(c64 v, float wr, float wi)
{
    float ar = lof(v), ai = hif(v);
    return pk(ar * wr - ai * wi, ar * wi + ai * wr);
}
__device__ __forceinline__ void cmul(float ar, float ai, float br, float bi,
                                     float& cr, float& ci)
{
    cr = ar * br - ai * bi;
    ci = ar * bi + ai * br;
}

// 8-point DFT (DIT), natural order, in-place, packed f32x2 arithmetic.
__device__ __forceinline__ void dft8p(c64* x, c64 NEG1, c64 CC)
{
    c64 t0 = addc(x[0], x[4]), t1 = subc(x[0], x[4], NEG1);
    c64 t2 = addc(x[2], x[6]), t3 = subc(x[2], x[6], NEG1);
    c64 E0 = addc(t0, t2),     E2 = subc(t0, t2, NEG1);
    c64 mt3 = mni(t3);
    c64 E1 = addc(t1, mt3),    E3 = subc(t1, mt3, NEG1);
    c64 s0 = addc(x[1], x[5]), s1 = subc(x[1], x[5], NEG1);
    c64 s2 = addc(x[3], x[7]), s3 = subc(x[3], x[7], NEG1);
    c64 O0 = addc(s0, s2),     O2 = subc(s0, s2, NEG1);
    c64 ms3 = mni(s3);
    c64 O1 = addc(s1, ms3),    O3 = subc(s1, ms3, NEG1);
    c64 P1 = sclc(addc(O1, mni(O1)), CC);
    c64 P2 = mni(O2);
    c64 P3 = sclc(subc(mni(O3), O3, NEG1), CC);
    x[0] = addc(E0, O0); x[4] = subc(E0, O0, NEG1);
    x[1] = addc(E1, P1); x[5] = subc(E1, P1, NEG1);
    x[2] = addc(E2, P2); x[6] = subc(E2, P2, NEG1);
    x[3] = addc(E3, P3); x[7] = subc(E3, P3, NEG1);
}

// Twiddle powers w^1..w^7 via depth-3 tree (shared by both rows).
__device__ __forceinline__ void wpowers(float w1r, float w1i, float* wr, float* wi)
{
    wr[1] = w1r; wi[1] = w1i;
    cmul(w1r, w1i, w1r, w1i, wr[2], wi[2]);
    cmul(wr[2], wi[2], w1r, w1i, wr[3], wi[3]);
    cmul(wr[2], wi[2], wr[2], wi[2], wr[4], wi[4]);
    cmul(wr[2], wi[2], wr[3], wi[3], wr[5], wi[5]);
    cmul(wr[3], wi[3], wr[3], wi[3], wr[6], wi[6]);
    cmul(wr[3], wi[3], wr[4], wi[4], wr[7], wi[7]);
}

// Stage<8> specialized per warp-uniform p (compile-time twiddles).
template <int P>
__device__ __forceinline__ void stage8_fixed(c64* zA, c64* zB, int tid,
                                             c64 NEG1, c64 CC)
{
    const int g    = tid & 63;
    const int base = g * 64 + P;
    const int q0   = Sc(base);

    c64 vA[8], vB[8];
    #pragma unroll
    for (int k = 0; k < 8; ++k) {
        int q = q0 ^ Sc(k * 8);
        vA[k] = zA[q];
        vB[k] = zB[q];
    }

    c64 xA[8], xB[8];
    xA[0] = vA[0]; xB[0] = vB[0];
    #pragma unroll
    for (int k = 1; k < 8; ++k) {
        if (P == 0) {
            xA[k] = vA[k];
            xB[k] = vB[k];
        } else {
            const float wr =  C64L(P * k);
            const float wi = -S64L(P * k);
            xA[k] = cmulp(vA[k], wr, wi);
            xB[k] = cmulp(vB[k], wr, wi);
        }
    }
    dft8p(xA, NEG1, CC);
    dft8p(xB, NEG1, CC);
    #pragma unroll
    for (int k = 0; k < 8; ++k) {
        int q = q0 ^ Sc(k * 8);
        zA[q] = xA[k];
        zB[q] = xB[k];
    }
}

// Stage<64>: runtime twiddles via wpowers (p varies within warp).
__device__ __forceinline__ void stage64_2(c64* zA, c64* zB, const float2* T,
                                          int tid, c64 NEG1, c64 CC)
{
    const int p = tid >> 3, g = tid & 7;
    const int base = g * 512 + p;
    const int q0   = Sc(base);

    c64 vA[8], vB[8];
    #pragma unroll
    for (int k = 0; k < 8; ++k) {
        int q = q0 ^ Sc(k * 64);
        vA[k] = zA[q];
        vB[k] = zB[q];
    }

    const float2 w1 = T[p * 16];
    float wr[8], wi[8];
    wpowers(w1.x, w1.y, wr, wi);

    c64 xA[8], xB[8];
    xA[0] = vA[0]; xB[0] = vB[0];
    #pragma unroll
    for (int k = 1; k < 8; ++k) {
        xA[k] = cmulp(vA[k], wr[k], wi[k]);
        xB[k] = cmulp(vB[k], wr[k], wi[k]);
    }
    dft8p(xA, NEG1, CC);
    dft8p(xB, NEG1, CC);
    #pragma unroll
    for (int k = 0; k < 8; ++k) {
        int q = q0 ^ Sc(k * 64);
        zA[q] = xA[k];
        zB[q] = xB[k];
    }
}

__global__ void __launch_bounds__(THREADS, 2) snr_fft_kernel(
    const float* __restrict__ outputs,
    const float* __restrict__ targets,
    float* __restrict__ d_out)
{
    extern __shared__ float smem_raw[];
    char* sb = reinterpret_cast<char*>(smem_raw);
    c64*    zA  = reinterpret_cast<c64*>(sb + ZA_OFF);    // 4096 c64
    c64*    zB  = reinterpret_cast<c64*>(sb + ZB_OFF);    // 4096 c64
    float2* T   = reinterpret_cast<float2*>(sb + T_OFF);  // 1032 float2
    float*  red = reinterpret_cast<float*>(sb + RED_OFF); // 60 floats

    const int tid = threadIdx.x;
    const uint32_t mbar = smem_u32(sb + MBAR_OFF);

    const c64 NEG1 = 0xBF800000BF800000ULL;              // (-1.0f, -1.0f)
    const c64 CC   = pk(0.70710678118654752f, 0.70710678118654752f);

    // One-time: async bulk copy of the twiddle table, then wait.
    if (tid == 0) {
        asm volatile("mbarrier.init.shared.b64 [%0], 1;" :: "r"(mbar) : "memory");
        asm volatile("mbarrier.arrive.expect_tx.shared.b64 _, [%0], %1;"
                     :: "r"(mbar), "r"((uint32_t)TAB_BYTES) : "memory");
        asm volatile("cp.async.bulk.shared::cluster.global.mbarrier::complete_tx::bytes "
                     "[%0], [%1], %2, [%3];"
                     :: "r"(smem_u32(T)), "l"((const void*)g_tab),
                        "r"((uint32_t)TAB_BYTES), "r"(mbar) : "memory");
    }
    __syncthreads();     // mbar init visible to all before try_wait
    asm volatile(
        "{\n\t.reg .pred P;\n"
        "WAITL%=:\n\t"
        "mbarrier.try_wait.parity.acquire.cta.shared::cta.b64 P, [%0], 0;\n\t"
        "@!P bra WAITL%=;\n\t}"
        :: "r"(mbar) : "memory");

    const int wid = tid >> 5, lane = tid & 31;

    // Persistent loop over row pairs.
    for (int pair = blockIdx.x; pair < N_PAIRS; pair += GRID_CTAS) {
        const int rowA = 2 * pair;
        const float tgtA = targets[rowA];
        const float tgtB = targets[rowA + 1];

        // L2 prefetch for this CTA's NEXT pair (64KB = 512 x 128B lines),
        // a full iteration (~8us) ahead of its demand loads.
        {
            int pf = pair + GRID_CTAS;
            if (pf < N_PAIRS) {
                const char* np = reinterpret_cast<const char*>(
                    outputs + (size_t)(2 * pf) * N_LEN) + tid * 128;
                asm volatile("prefetch.global.L2 [%0];" :: "l"(np));
            }
        }

        // Fused coalesced load + stage 1 for BOTH rows (16 LDG.64, MLP=16).
        {
            const c64* xrA = reinterpret_cast<const c64*>(outputs) + (size_t)rowA * M_FFT;
            const c64* xrB = xrA + M_FFT;
            c64 a[8], b[8];
            #pragma unroll
            for (int k = 0; k < 8; ++k) {
                a[k] = xrA[tid + (k << 9)];
                b[k] = xrB[tid + (k << 9)];
            }
            dft8p(a, NEG1, CC);
            dft8p(b, NEG1, CC);
            const int t8 = ((tid & 7) << 6) | (((tid >> 3) & 7) << 3) | (tid >> 6);
            const int q0 = Sc(t8 << 3);
            #pragma unroll
            for (int k = 0; k < 8; ++k) {  // Sc(k) = k for k < 8
                zA[q0 ^ k] = a[k];
                zB[q0 ^ k] = b[k];
            }
        }
        __syncthreads();     // stage-1 data published

        // Stage <8>: warp-uniform p = tid>>6 -> compile-time twiddles.
        switch (tid >> 6) {
            case 0: stage8_fixed<0>(zA, zB, tid, NEG1, CC); break;
            case 1: stage8_fixed<1>(zA, zB, tid, NEG1, CC); break;
            case 2: stage8_fixed<2>(zA, zB, tid, NEG1, CC); break;
            case 3: stage8_fixed<3>(zA, zB, tid, NEG1, CC); break;
            case 4: stage8_fixed<4>(zA, zB, tid, NEG1, CC); break;
            case 5: stage8_fixed<5>(zA, zB, tid, NEG1, CC); break;
            case 6: stage8_fixed<6>(zA, zB, tid, NEG1, CC); break;
            default: stage8_fixed<7>(zA, zB, tid, NEG1, CC); break;
        }
        __syncthreads();

        stage64_2(zA, zB, T, tid, NEG1, CC);
        __syncthreads();

        // Stage L=512: load BOTH rows first, then compute.
        c64 bA[4], bB[4];
        {
            const int q0 = Sc(tid);
            c64 vA[8], vB[8];
            #pragma unroll
            for (int k = 0; k < 8; ++k) {
                int q = q0 ^ Sc(k * 512);
                vA[k] = zA[q];
                vB[k] = zB[q];
            }

            const float2 w1 = T[2 * tid];  // exp(-2*pi*i*tid/4096)
            float wr[8], wi[8];
            wpowers(w1.x, w1.y, wr, wi);

            c64 xA[8], xB[8];
            xA[0] = vA[0]; xB[0] = vB[0];
            #pragma unroll
            for (int k = 1; k < 8; ++k) {
                xA[k] = cmulp(vA[k], wr[k], wi[k]);
                xB[k] = cmulp(vB[k], wr[k], wi[k]);
            }
            dft8p(xA, NEG1, CC);
            dft8p(xB, NEG1, CC);

            // Publish only the index range the epilogue reads: [272, 3824].
            #pragma unroll
            for (int k = 0; k < 8; ++k) {
                bool need = (k == 0) ? (tid >= 272)
                          : (k == 7) ? (tid <= 240)
                          : true;
                if (need) {
                    int q = q0 ^ Sc(k * 512);
                    zA[q] = xA[k];
                    zB[q] = xB[k];
                }
            }
            #pragma unroll
            for (int k = 0; k < 4; ++k) { bA[k] = xA[k]; bB[k] = xB[k]; }
        }
        __syncthreads();     // final Z published for both rows

        // Weight-free band sums over k in [273, 1706] for both rows.
        // Unpack twiddle folded: W(tid + 512c) = T[tid] * exp(-i*pi*c/8).
        const float2 Wt = T[tid];
        const float ecr[4] = { 1.0f, 0.92387953251128675613f,
                               0.70710678118654752440f, 0.38268343236508977173f };
        const float eci[4] = { 0.0f, -0.38268343236508977173f,
                              -0.70710678118654752440f, -0.92387953251128675613f };
        float bandA0 = 0.0f, bandA1 = 0.0f, bandB0 = 0.0f, bandB1 = 0.0f;
        #pragma unroll
        for (int c = 0; c < 4; ++c) {
            int k = tid + (c << 9);
            bool valid = (c == 1) || (c == 2) ||
                         (c == 0 ? (tid >= MIN_IDX) : (k <= MAX_IDX - 1));
            if (valid) {
                float Wr, Wi;
                if (c == 0) { Wr = Wt.x; Wi = Wt.y; }
                else        { cmul(Wt.x, Wt.y, ecr[c], eci[c], Wr, Wi); }
                int q2 = Sc(M_FFT - k);
                {   // row A
                    c64 Z2p = zA[q2];
                    float Z2r = lof(Z2p), Z2i = hif(Z2p);
                    float xrc = lof(bA[c]), xic = hif(bA[c]);
                    float Er = 0.5f * (xrc + Z2r);
                    float Ei = 0.5f * (xic - Z2i);
                    float Or = 0.5f * (xic + Z2i);
                    float Oi = 0.5f * (Z2r - xrc);
                    float Xr = Er + Wr * Or - Wi * Oi;
                    float Xi = Ei + Wr * Oi + Wi * Or;
                    float pw = (Xr * Xr + Xi * Xi) * (1.0f / (float)N_LEN);
                    if (c & 1) bandA1 += pw; else bandA0 += pw;
                }
                {   // row B
                    c64 Z2p = zB[q2];
                    float Z2r = lof(Z2p), Z2i = hif(Z2p);
                    float xrc = lof(bB[c]), xic = hif(bB[c]);
                    float Er = 0.5f * (xrc + Z2r);
                    float Ei = 0.5f * (xic - Z2i);
                    float Or = 0.5f * (xic + Z2i);
                    float Oi = 0.5f * (Z2r - xrc);
                    float Xr = Er + Wr * Or - Wi * Oi;
                    float Xi = Ei + Wr * Oi + Wi * Or;
                    float pw = (Xr * Xr + Xi * Xi) * (1.0f / (float)N_LEN);
                    if (c & 1) bandB1 += pw; else bandB0 += pw;
                }
            }
        }
        float bandA = bandA0 + bandA1;
        float bandB = bandB0 + bandB1;

        // Special bins: threads 0..5 row A, threads 8..13 row B.
        float spec_sig = 0.0f, spec_corr = 0.0f;
        bool isSpec = (tid < 6) || (tid >= 8 && tid < 14);
        if (isSpec) {
            bool isB = tid >= 8;
            int s = isB ? tid - 8 : tid;
            const int   joff[6] = { -1, 0, 1, -1, 0, 1 };
            const float uw[6]   = { 0.5f, 1.0f, 0.5f, 0.0f, 1.0f, 0.0f };
            const float mw[6]   = { 0.5f, 1.0f, 0.5f, 1.0f, 1.0f, 1.0f };
            const float tgt = isB ? tgtB : tgtA;
            int ib = (int)floorf(tgt / DF) - 1;
            if (ib < 0) ib = 0;
            if (ib > M_FFT - 3) ib = M_FFT - 3;
            int r = ib;
            float best = fabsf((float)ib * DF - tgt);
            #pragma unroll
            for (int i = 1; i <= 3; ++i) {
                float d = fabsf((float)(ib + i) * DF - tgt);
                if (d < best) { best = d; r = ib + i; }
            }
            int j = (s < 3 ? r : 2 * r) + joff[s];
            const c64* zp = isB ? zB : zA;
            c64 Z1p = zp[Sc(j)];
            c64 Z2p = zp[Sc(M_FFT - j)];
            float Z1r = lof(Z1p), Z1i = hif(Z1p);
            float Z2r = lof(Z2p), Z2i = hif(Z2p);
            float Er = 0.5f * (Z1r + Z2r);
            float Ei = 0.5f * (Z1i - Z2i);
            float Or = 0.5f * (Z1i + Z2i);
            float Oi = 0.5f * (Z2r - Z1r);
            float Ws, Wc;
            sincospif(-(float)j * (1.0f / 4096.0f), &Ws, &Wc);
            float Xr = Er + Wc * Or - Ws * Oi;
            float Xi = Ei + Wc * Oi + Ws * Or;
            float P = (Xr * Xr + Xi * Xi) * (1.0f / (float)N_LEN);
            spec_sig  = uw[s] * P;
            spec_corr = (j >= MIN_IDX && j < MAX_IDX) ? mw[s] * P : 0.0f;
        }

        // Band reductions (both rows) within warps.
        #pragma unroll
        for (int o = 16; o > 0; o >>= 1) {
            bandA += __shfl_down_sync(0xffffffffu, bandA, o);
            bandB += __shfl_down_sync(0xffffffffu, bandB, o);
        }
        __syncthreads();     // z + red reads of previous phase complete
        if (lane == 0) { red[wid] = bandA; red[16 + wid] = bandB; }
        if (isSpec) {
            bool isB = tid >= 8;
            int s = isB ? tid - 8 : tid;
            int off = isB ? 44 : 32;
            red[off + s]     = spec_sig;
            red[off + 6 + s] = spec_corr;
        }
        __syncthreads();

        if (tid < 2) {
            int boff = tid ? 16 : 0;
            int soff = tid ? 44 : 32;
            float Bt = 0.0f;
            #pragma unroll
            for (int i = 0; i < 16; ++i) Bt += red[boff + i];
            float Sg = 0.0f, Cr = 0.0f;
            #pragma unroll
            for (int i = 0; i < 6; ++i) { Sg += red[soff + i]; Cr += red[soff + 6 + i]; }
            g_losses[rowA + tid] = -10.0f * log10f(Sg / ((Bt - Cr) + 1.0f));
            __threadfence();
        }
        __syncthreads();     // closes iteration: losses stored, red/z reusable
    }

    // One arrival per CTA after all its pairs are stored + fenced.
    __shared__ bool is_last;
    if (tid == 0) {
        unsigned int old = atomicAdd(&g_ctr, 1u);
        is_last = (old == (unsigned int)(GRID_CTAS - 1));
    }
    __syncthreads();

    // Last CTA computes the mean (fixed-order, deterministic), resets ctr.
    if (is_last) {
        float s = 0.0f;
        for (int i = tid; i < B_ROWS; i += THREADS) s += g_losses[i];
        #pragma unroll
        for (int o = 16; o > 0; o >>= 1) s += __shfl_down_sync(0xffffffffu, s, o);
        __syncthreads();
        if (lane == 0) red[wid] = s;
        __syncthreads();
        if (tid == 0) {
            float t = 0.0f;
            #pragma unroll
            for (int i = 0; i < 16; ++i) t += red[i];
            d_out[0] = t * (1.0f / (float)B_ROWS);
            g_ctr = 0;
        }
    }
}

extern "C" void kernel_launch(void* const* d_in, const int* in_sizes, int n_in,
                              void* d_out, int out_size)
{
    const float* outputs = (const float*)d_in[0];   // [4096, 8192] f32
    const float* targets = (const float*)d_in[1];   // [4096, 1]    f32
    (void)in_sizes; (void)n_in; (void)out_size;

    cudaFuncSetAttribute(snr_fft_kernel,
                         cudaFuncAttributeMaxDynamicSharedMemorySize, SMEM_TOTAL);

    twiddle_init_kernel<<<3, 512>>>();
    snr_fft_kernel<<<GRID_CTAS, THREADS, SMEM_TOTAL>>>(outputs, targets, (float*)d_out);
}

// round 15
// speedup vs baseline: 1.3122x; 1.3122x over previous
#include <cuda_runtime.h>
#include <cstdint>

#define B_ROWS 4096
#define N_LEN  8192
#define M_FFT  4096
#define THREADS 512
#define GRID_CTAS (B_ROWS / 2)
#define WAVE_CTAS 296        // 148 SMs x 2 CTAs/SM

#define MIN_IDX 273           // argmin |f - 40/60|  (f[i] = i*5/2048, exact fp32)
#define MAX_IDX 1707          // argmin |f - 250/60|  (band = [273, 1707) )
#define DF 0.00244140625f     // 10/4096, exact fp32

// Twiddle table: T[p] = exp(-i*pi*p/4096), p in [0,1028); padded to 1032.
#define TAB_N    1032
#define TAB_BYTES (TAB_N * 8)           // 8256

// smem layout (bytes from dynamic base)
#define ZA_OFF   0
#define ZB_OFF   32768
#define T_OFF    65536
#define MBAR_OFF (T_OFF + TAB_BYTES)    // 73792
#define SMEM_TOTAL (MBAR_OFF + 16)      // 73808

__device__ float g_losses[B_ROWS];
__device__ __align__(16) float2 g_tab[TAB_N];
__device__ unsigned int g_ctr = 0;      // last-CTA counter (self-resetting)

__global__ void twiddle_init_kernel()
{
    int p = blockIdx.x * blockDim.x + threadIdx.x;
    if (p < TAB_N) {
        float s, c;
        sincospif(-(float)p * (1.0f / 4096.0f), &s, &c);
        g_tab[p] = make_float2(c, s);
    }
}

__device__ __forceinline__ uint32_t smem_u32(const void* p)
{
    uint32_t a;
    asm("{ .reg .u64 t; cvta.to.shared.u64 t, %1; cvt.u32.u64 %0, t; }"
        : "=r"(a) : "l"(p));
    return a;
}

// GF(2)-linear swizzle on c64 indices (conflict-free for all stage
// patterns; validated R5-R13, rel_err 0).
__host__ __device__ constexpr int Sc(int i)
{
    return i ^ ((i >> 6) & 1) ^ ((i >> 5) & 0xC) ^ ((i >> 8) & 0xE);
}

// cos(pi*m/32) and sin(pi*m/32) literals, m in [0, 49] (stage<8> twiddles).
__device__ __constant__ const float C64c[50] = {
 1.0f, 0.99518472667219693f, 0.98078528040323044f, 0.95694033573220886f,
 0.92387953251128676f, 0.88192126434835503f, 0.83146961230254524f,
 0.77301045336273696f, 0.70710678118654752f, 0.63439328416364549f,
 0.55557023301960222f, 0.47139673682599764f, 0.38268343236508977f,
 0.29028467725446233f, 0.19509032201612827f, 0.09801714032956060f,
 0.0f, -0.09801714032956060f, -0.19509032201612827f, -0.29028467725446233f,
 -0.38268343236508977f, -0.47139673682599764f, -0.55557023301960222f,
 -0.63439328416364549f, -0.70710678118654752f, -0.77301045336273696f,
 -0.83146961230254524f, -0.88192126434835503f, -0.92387953251128676f,
 -0.95694033573220886f, -0.98078528040323044f, -0.99518472667219693f,
 -1.0f, -0.99518472667219693f, -0.98078528040323044f, -0.95694033573220886f,
 -0.92387953251128676f, -0.88192126434835503f, -0.83146961230254524f,
 -0.77301045336273696f, -0.70710678118654752f, -0.63439328416364549f,
 -0.55557023301960222f, -0.47139673682599764f, -0.38268343236508977f,
 -0.29028467725446233f, -0.19509032201612827f, -0.09801714032956060f,
 0.0f, 0.09801714032956060f };
__device__ __constant__ const float S64c[50] = {
 0.0f, 0.09801714032956060f, 0.19509032201612827f, 0.29028467725446233f,
 0.38268343236508977f, 0.47139673682599764f, 0.55557023301960222f,
 0.63439328416364549f, 0.70710678118654752f, 0.77301045336273696f,
 0.83146961230254524f, 0.88192126434835503f, 0.92387953251128676f,
 0.95694033573220886f, 0.98078528040323044f, 0.99518472667219693f,
 1.0f, 0.99518472667219693f, 0.98078528040323044f, 0.95694033573220886f,
 0.92387953251128676f, 0.88192126434835503f, 0.83146961230254524f,
 0.77301045336273696f, 0.70710678118654752f, 0.63439328416364549f,
 0.55557023301960222f, 0.47139673682599764f, 0.38268343236508977f,
 0.29028467725446233f, 0.19509032201612827f, 0.09801714032956060f,
 0.0f, -0.09801714032956060f, -0.19509032201612827f, -0.29028467725446233f,
 -0.38268343236508977f, -0.47139673682599764f, -0.55557023301960222f,
 -0.63439328416364549f, -0.70710678118654752f, -0.77301045336273696f,
 -0.83146961230254524f, -0.88192126434835503f, -0.92387953251128676f,
 -0.95694033573220886f, -0.98078528040323044f, -0.99518472667219693f,
 -1.0f, -0.99518472667219693f };

#define C64L(m) (C64c[m])
#define S64L(m) (S64c[m])

// ---------- packed f32x2 complex helpers ----------
typedef unsigned long long c64;      // (real, imag) packed as 2 x f32

__device__ __forceinline__ c64 pk(float lo, float hi)
{
    c64 r;
    asm("mov.b64 %0, {%1, %2};" : "=l"(r) : "f"(lo), "f"(hi));
    return r;
}
__device__ __forceinline__ float lof(c64 a)
{
    float f;
    asm("{ .reg .f32 h; mov.b64 {%0, h}, %1; }" : "=f"(f) : "l"(a));
    return f;
}
__device__ __forceinline__ float hif(c64 a)
{
    float f;
    asm("{ .reg .f32 l; mov.b64 {l, %0}, %1; }" : "=f"(f) : "l"(a));
    return f;
}
__device__ __forceinline__ c64 addc(c64 a, c64 b)
{
    c64 r;
    asm("add.rn.f32x2 %0, %1, %2;" : "=l"(r) : "l"(a), "l"(b));
    return r;
}
__device__ __forceinline__ c64 subc(c64 a, c64 b, c64 NEG1)
{
    c64 r;
    asm("fma.rn.f32x2 %0, %1, %2, %3;" : "=l"(r) : "l"(b), "l"(NEG1), "l"(a));
    return r;
}
__device__ __forceinline__ c64 sclc(c64 a, c64 s)
{
    c64 r;
    asm("mul.rn.f32x2 %0, %1, %2;" : "=l"(r) : "l"(a), "l"(s));
    return r;
}
// multiply by -i: (r, i) -> (i, -r)
__device__ __forceinline__ c64 mni(c64 a)
{
    return pk(hif(a), -lof(a));
}
// scalar cmul producing packed result: v * (wr + i*wi)
__device__ __forceinline__ c64 cmulp(c64 v, float wr, float wi)
{
    float ar = lof(v), ai = hif(v);
    return pk(ar * wr - ai * wi, ar * wi + ai * wr);
}
__device__ __forceinline__ void cmul(float ar, float ai, float br, float bi,
                                     float& cr, float& ci)
{
    cr = ar * br - ai * bi;
    ci = ar * bi + ai * br;
}

// 8-point DFT (DIT), natural order, in-place, packed f32x2 arithmetic.
__device__ __forceinline__ void dft8p(c64* x, c64 NEG1, c64 CC)
{
    c64 t0 = addc(x[0], x[4]), t1 = subc(x[0], x[4], NEG1);
    c64 t2 = addc(x[2], x[6]), t3 = subc(x[2], x[6], NEG1);
    c64 E0 = addc(t0, t2),     E2 = subc(t0, t2, NEG1);
    c64 mt3 = mni(t3);
    c64 E1 = addc(t1, mt3),    E3 = subc(t1, mt3, NEG1);
    c64 s0 = addc(x[1], x[5]), s1 = subc(x[1], x[5], NEG1);
    c64 s2 = addc(x[3], x[7]), s3 = subc(x[3], x[7], NEG1);
    c64 O0 = addc(s0, s2),     O2 = subc(s0, s2, NEG1);
    c64 ms3 = mni(s3);
    c64 O1 = addc(s1, ms3),    O3 = subc(s1, ms3, NEG1);
    c64 P1 = sclc(addc(O1, mni(O1)), CC);
    c64 P2 = mni(O2);
    c64 P3 = sclc(subc(mni(O3), O3, NEG1), CC);
    x[0] = addc(E0, O0); x[4] = subc(E0, O0, NEG1);
    x[1] = addc(E1, P1); x[5] = subc(E1, P1, NEG1);
    x[2] = addc(E2, P2); x[6] = subc(E2, P2, NEG1);
    x[3] = addc(E3, P3); x[7] = subc(E3, P3, NEG1);
}

// Twiddle powers w^1..w^7 via depth-3 tree (shared by both rows).
__device__ __forceinline__ void wpowers(float w1r, float w1i, float* wr, float* wi)
{
    wr[1] = w1r; wi[1] = w1i;
    cmul(w1r, w1i, w1r, w1i, wr[2], wi[2]);
    cmul(wr[2], wi[2], w1r, w1i, wr[3], wi[3]);
    cmul(wr[2], wi[2], wr[2], wi[2], wr[4], wi[4]);
    cmul(wr[2], wi[2], wr[3], wi[3], wr[5], wi[5]);
    cmul(wr[3], wi[3], wr[3], wi[3], wr[6], wi[6]);
    cmul(wr[3], wi[3], wr[4], wi[4], wr[7], wi[7]);
}

// Stage<8> specialized per warp-uniform p (compile-time twiddles).
template <int P>
__device__ __forceinline__ void stage8_fixed(c64* zA, c64* zB, int tid,
                                             c64 NEG1, c64 CC)
{
    const int g    = tid & 63;
    const int base = g * 64 + P;
    const int q0   = Sc(base);

    c64 vA[8], vB[8];
    #pragma unroll
    for (int k = 0; k < 8; ++k) {
        int q = q0 ^ Sc(k * 8);
        vA[k] = zA[q];
        vB[k] = zB[q];
    }

    c64 xA[8], xB[8];
    xA[0] = vA[0]; xB[0] = vB[0];
    #pragma unroll
    for (int k = 1; k < 8; ++k) {
        if (P == 0) {
            xA[k] = vA[k];
            xB[k] = vB[k];
        } else {
            const float wr =  C64L(P * k);
            const float wi = -S64L(P * k);
            xA[k] = cmulp(vA[k], wr, wi);
            xB[k] = cmulp(vB[k], wr, wi);
        }
    }
    dft8p(xA, NEG1, CC);
    dft8p(xB, NEG1, CC);
    #pragma unroll
    for (int k = 0; k < 8; ++k) {
        int q = q0 ^ Sc(k * 8);
        zA[q] = xA[k];
        zB[q] = xB[k];
    }
}

// Stage<64>: runtime twiddles via wpowers (p varies within warp).
__device__ __forceinline__ void stage64_2(c64* zA, c64* zB, const float2* T,
                                          int tid, c64 NEG1, c64 CC)
{
    const int p = tid >> 3, g = tid & 7;
    const int base = g * 512 + p;
    const int q0   = Sc(base);

    c64 vA[8], vB[8];
    #pragma unroll
    for (int k = 0; k < 8; ++k) {
        int q = q0 ^ Sc(k * 64);
        vA[k] = zA[q];
        vB[k] = zB[q];
    }

    const float2 w1 = T[p * 16];
    float wr[8], wi[8];
    wpowers(w1.x, w1.y, wr, wi);

    c64 xA[8], xB[8];
    xA[0] = vA[0]; xB[0] = vB[0];
    #pragma unroll
    for (int k = 1; k < 8; ++k) {
        xA[k] = cmulp(vA[k], wr[k], wi[k]);
        xB[k] = cmulp(vB[k], wr[k], wi[k]);
    }
    dft8p(xA, NEG1, CC);
    dft8p(xB, NEG1, CC);
    #pragma unroll
    for (int k = 0; k < 8; ++k) {
        int q = q0 ^ Sc(k * 64);
        zA[q] = xA[k];
        zB[q] = xB[k];
    }
}

__global__ void __launch_bounds__(THREADS, 2) snr_fft_kernel(
    const float* __restrict__ outputs,
    const float* __restrict__ targets,
    float* __restrict__ d_out)
{
    extern __shared__ float smem_raw[];
    char* sb = reinterpret_cast<char*>(smem_raw);
    c64*    zA = reinterpret_cast<c64*>(sb + ZA_OFF);    // 4096 c64
    c64*    zB = reinterpret_cast<c64*>(sb + ZB_OFF);    // 4096 c64
    float2* T  = reinterpret_cast<float2*>(sb + T_OFF);  // 1032 float2

    const int tid = threadIdx.x;
    const int rowA = 2 * blockIdx.x;
    const uint32_t mbar = smem_u32(sb + MBAR_OFF);

    const c64 NEG1 = 0xBF800000BF800000ULL;              // (-1.0f, -1.0f)
    const c64 CC   = pk(0.70710678118654752f, 0.70710678118654752f);

    // Hoist targets (used late; pull latency to the front).
    const float tgtA = targets[rowA];
    const float tgtB = targets[rowA + 1];

    // Async bulk copy of the twiddle table (overlaps row loads + stage 1).
    if (tid == 0) {
        asm volatile("mbarrier.init.shared.b64 [%0], 1;" :: "r"(mbar) : "memory");
        asm volatile("mbarrier.arrive.expect_tx.shared.b64 _, [%0], %1;"
                     :: "r"(mbar), "r"((uint32_t)TAB_BYTES) : "memory");
        asm volatile("cp.async.bulk.shared::cluster.global.mbarrier::complete_tx::bytes "
                     "[%0], [%1], %2, [%3];"
                     :: "r"(smem_u32(T)), "l"((const void*)g_tab),
                        "r"((uint32_t)TAB_BYTES), "r"(mbar) : "memory");
    }

    // Fused coalesced load + stage 1 for BOTH rows (16 LDG.64, MLP=16).
    {
        const c64* xrA = reinterpret_cast<const c64*>(outputs) + (size_t)rowA * M_FFT;
        const c64* xrB = xrA + M_FFT;
        c64 a[8], b[8];
        #pragma unroll
        for (int k = 0; k < 8; ++k) {
            a[k] = xrA[tid + (k << 9)];
            b[k] = xrB[tid + (k << 9)];
        }

        // L2 prefetch one AND two waves ahead (64KB = 512 x 128B lines per
        // CTA). Issued after the demand loads so they never delay them; the
        // two-wave-deep touch covers wave-boundary CTAs whose one-wave
        // prefetch may still be in flight when they start.
        {
            int pf = blockIdx.x + WAVE_CTAS;
            if (pf < GRID_CTAS) {
                const char* np = reinterpret_cast<const char*>(
                    outputs + (size_t)(2 * pf) * N_LEN) + tid * 128;
                asm volatile("prefetch.global.L2 [%0];" :: "l"(np));
            }
            int pf2 = blockIdx.x + 2 * WAVE_CTAS;
            if (pf2 < GRID_CTAS) {
                const char* np2 = reinterpret_cast<const char*>(
                    outputs + (size_t)(2 * pf2) * N_LEN) + tid * 128;
                asm volatile("prefetch.global.L2 [%0];" :: "l"(np2));
            }
        }

        dft8p(a, NEG1, CC);
        dft8p(b, NEG1, CC);
        const int t8 = ((tid & 7) << 6) | (((tid >> 3) & 7) << 3) | (tid >> 6);
        const int q0 = Sc(t8 << 3);
        #pragma unroll
        for (int k = 0; k < 8; ++k) {      // Sc(k) = k for k < 8
            zA[q0 ^ k] = a[k];
            zB[q0 ^ k] = b[k];
        }
    }
    __syncthreads();     // stage-1 data published; also orders mbar init

    // Stage <8>: warp-uniform p = tid>>6 -> compile-time twiddles.
    switch (tid >> 6) {
        case 0: stage8_fixed<0>(zA, zB, tid, NEG1, CC); break;
        case 1: stage8_fixed<1>(zA, zB, tid, NEG1, CC); break;
        case 2: stage8_fixed<2>(zA, zB, tid, NEG1, CC); break;
        case 3: stage8_fixed<3>(zA, zB, tid, NEG1, CC); break;
        case 4: stage8_fixed<4>(zA, zB, tid, NEG1, CC); break;
        case 5: stage8_fixed<5>(zA, zB, tid, NEG1, CC); break;
        case 6: stage8_fixed<6>(zA, zB, tid, NEG1, CC); break;
        default: stage8_fixed<7>(zA, zB, tid, NEG1, CC); break;
    }
    __syncthreads();

    // Wait for the table before first T use (stage<64>).
    asm volatile(
        "{\n\t.reg .pred P;\n"
        "WAITL%=:\n\t"
        "mbarrier.try_wait.parity.acquire.cta.shared::cta.b64 P, [%0], 0;\n\t"
        "@!P bra WAITL%=;\n\t}"
        :: "r"(mbar) : "memory");

    stage64_2(zA, zB, T, tid, NEG1, CC);
    __syncthreads();

    // Stage L=512: load BOTH rows first, then compute.
    c64 bA[4], bB[4];
    {
        const int q0 = Sc(tid);
        c64 vA[8], vB[8];
        #pragma unroll
        for (int k = 0; k < 8; ++k) {
            int q = q0 ^ Sc(k * 512);
            vA[k] = zA[q];
            vB[k] = zB[q];
        }

        const float2 w1 = T[2 * tid];      // exp(-2*pi*i*tid/4096)
        float wr[8], wi[8];
        wpowers(w1.x, w1.y, wr, wi);

        c64 xA[8], xB[8];
        xA[0] = vA[0]; xB[0] = vB[0];
        #pragma unroll
        for (int k = 1; k < 8; ++k) {
            xA[k] = cmulp(vA[k], wr[k], wi[k]);
            xB[k] = cmulp(vB[k], wr[k], wi[k]);
        }
        dft8p(xA, NEG1, CC);
        dft8p(xB, NEG1, CC);

        // Publish only the index range the epilogue reads: [272, 3824].
        #pragma unroll
        for (int k = 0; k < 8; ++k) {
            bool need = (k == 0) ? (tid >= 272)
                      : (k == 7) ? (tid <= 240)
                      : true;
            if (need) {
                int q = q0 ^ Sc(k * 512);
                zA[q] = xA[k];
                zB[q] = xB[k];
            }
        }
        #pragma unroll
        for (int k = 0; k < 4; ++k) { bA[k] = xA[k]; bB[k] = xB[k]; }
    }
    __syncthreads();     // final Z published for both rows

    // Weight-free band sums over k in [273, 1706] for both rows.
    // Unpack twiddle folded: W(tid + 512c) = T[tid] * exp(-i*pi*c/8).
    const float2 Wt = T[tid];
    const float ecr[4] = { 1.0f, 0.92387953251128675613f,
                           0.70710678118654752440f, 0.38268343236508977173f };
    const float eci[4] = { 0.0f, -0.38268343236508977173f,
                          -0.70710678118654752440f, -0.92387953251128675613f };
    float bandA0 = 0.0f, bandA1 = 0.0f, bandB0 = 0.0f, bandB1 = 0.0f;
    #pragma unroll
    for (int c = 0; c < 4; ++c) {
        int k = tid + (c << 9);
        bool valid = (c == 1) || (c == 2) ||
                     (c == 0 ? (tid >= MIN_IDX) : (k <= MAX_IDX - 1));
        if (valid) {
            float Wr, Wi;
            if (c == 0) { Wr = Wt.x; Wi = Wt.y; }
            else        { cmul(Wt.x, Wt.y, ecr[c], eci[c], Wr, Wi); }
            int q2 = Sc(M_FFT - k);
            {   // row A
                c64 Z2p = zA[q2];
                float Z2r = lof(Z2p), Z2i = hif(Z2p);
                float xrc = lof(bA[c]), xic = hif(bA[c]);
                float Er = 0.5f * (xrc + Z2r);
                float Ei = 0.5f * (xic - Z2i);
                float Or = 0.5f * (xic + Z2i);
                float Oi = 0.5f * (Z2r - xrc);
                float Xr = Er + Wr * Or - Wi * Oi;
                float Xi = Ei + Wr * Oi + Wi * Or;
                float pw = (Xr * Xr + Xi * Xi) * (1.0f / (float)N_LEN);
                if (c & 1) bandA1 += pw; else bandA0 += pw;
            }
            {   // row B
                c64 Z2p = zB[q2];
                float Z2r = lof(Z2p), Z2i = hif(Z2p);
                float xrc = lof(bB[c]), xic = hif(bB[c]);
                float Er = 0.5f * (xrc + Z2r);
                float Ei = 0.5f * (xic - Z2i);
                float Or = 0.5f * (xic + Z2i);
                float Oi = 0.5f * (Z2r - xrc);
                float Xr = Er + Wr * Or - Wi * Oi;
                float Xi = Ei + Wr * Oi + Wi * Or;
                float pw = (Xr * Xr + Xi * Xi) * (1.0f / (float)N_LEN);
                if (c & 1) bandB1 += pw; else bandB0 += pw;
            }
        }
    }
    float bandA = bandA0 + bandA1;
    float bandB = bandB0 + bandB1;

    // Special bins: threads 0..5 do row A, threads 8..13 do row B.
    float spec_sig = 0.0f, spec_corr = 0.0f;
    bool isSpec = (tid < 6) || (tid >= 8 && tid < 14);
    if (isSpec) {
        bool isB = tid >= 8;
        int s = isB ? tid - 8 : tid;
        const int   joff[6] = { -1, 0, 1, -1, 0, 1 };
        const float uw[6]   = { 0.5f, 1.0f, 0.5f, 0.0f, 1.0f, 0.0f };
        const float mw[6]   = { 0.5f, 1.0f, 0.5f, 1.0f, 1.0f, 1.0f };
        const float tgt = isB ? tgtB : tgtA;
        int ib = (int)floorf(tgt / DF) - 1;
        if (ib < 0) ib = 0;
        if (ib > M_FFT - 3) ib = M_FFT - 3;
        int r = ib;
        float best = fabsf((float)ib * DF - tgt);
        #pragma unroll
        for (int i = 1; i <= 3; ++i) {
            float d = fabsf((float)(ib + i) * DF - tgt);
            if (d < best) { best = d; r = ib + i; }
        }
        int j = (s < 3 ? r : 2 * r) + joff[s];
        const c64* zp = isB ? zB : zA;
        c64 Z1p = zp[Sc(j)];
        c64 Z2p = zp[Sc(M_FFT - j)];
        float Z1r = lof(Z1p), Z1i = hif(Z1p);
        float Z2r = lof(Z2p), Z2i = hif(Z2p);
        float Er = 0.5f * (Z1r + Z2r);
        float Ei = 0.5f * (Z1i - Z2i);
        float Or = 0.5f * (Z1i + Z2i);
        float Oi = 0.5f * (Z2r - Z1r);
        float Ws, Wc;
        sincospif(-(float)j * (1.0f / 4096.0f), &Ws, &Wc);
        float Xr = Er + Wc * Or - Ws * Oi;
        float Xi = Ei + Wc * Oi + Ws * Or;
        float P = (Xr * Xr + Xi * Xi) * (1.0f / (float)N_LEN);
        spec_sig  = uw[s] * P;
        spec_corr = (j >= MIN_IDX && j < MAX_IDX) ? mw[s] * P : 0.0f;
    }

    // Band reductions (both rows) within warps.
    #pragma unroll
    for (int o = 16; o > 0; o >>= 1) {
        bandA += __shfl_down_sync(0xffffffffu, bandA, o);
        bandB += __shfl_down_sync(0xffffffffu, bandB, o);
    }
    const int wid = tid >> 5, lane = tid & 31;
    float* red = reinterpret_cast<float*>(T);   // T reads done after this barrier
    __syncthreads();
    if (lane == 0) { red[wid] = bandA; red[16 + wid] = bandB; }
    if (isSpec) {
        bool isB = tid >= 8;
        int s = isB ? tid - 8 : tid;
        int off = isB ? 44 : 32;
        red[off + s]     = spec_sig;
        red[off + 6 + s] = spec_corr;
    }
    __syncthreads();

    __shared__ bool is_last;
    if (tid < 2) {
        int boff = tid ? 16 : 0;
        int soff = tid ? 44 : 32;
        float Bt = 0.0f;
        #pragma unroll
        for (int i = 0; i < 16; ++i) Bt += red[boff + i];
        float Sg = 0.0f, Cr = 0.0f;
        #pragma unroll
        for (int i = 0; i < 6; ++i) { Sg += red[soff + i]; Cr += red[soff + 6 + i]; }
        g_losses[rowA + tid] = -10.0f * log10f(Sg / ((Bt - Cr) + 1.0f));
        __threadfence();
    }
    __syncthreads();
    if (tid == 0) {
        unsigned int old = atomicAdd(&g_ctr, 1u);
        is_last = (old == (unsigned int)(GRID_CTAS - 1));
    }
    __syncthreads();

    // Last CTA computes the mean (fixed-order, deterministic), resets ctr.
    if (is_last) {
        float s = 0.0f;
        for (int i = tid; i < B_ROWS; i += THREADS) s += g_losses[i];
        #pragma unroll
        for (int o = 16; o > 0; o >>= 1) s += __shfl_down_sync(0xffffffffu, s, o);
        __syncthreads();
        if (lane == 0) red[wid] = s;
        __syncthreads();
        if (tid == 0) {
            float t = 0.0f;
            #pragma unroll
            for (int i = 0; i < 16; ++i) t += red[i];
            d_out[0] = t * (1.0f / (float)B_ROWS);
            g_ctr = 0;
        }
    }
}

extern "C" void kernel_launch(void* const* d_in, const int* in_sizes, int n_in,
                              void* d_out, int out_size)
{
    const float* outputs = (const float*)d_in[0];   // [4096, 8192] f32
    const float* targets = (const float*)d_in[1];   // [4096, 1]    f32
    (void)in_sizes; (void)n_in; (void)out_size;

    cudaFuncSetAttribute(snr_fft_kernel,
                         cudaFuncAttributeMaxDynamicSharedMemorySize, SMEM_TOTAL);

    twiddle_init_kernel<<<3, 512>>>();
    snr_fft_kernel<<<GRID_CTAS, THREADS, SMEM_TOTAL>>>(outputs, targets, (float*)d_out);
}

// round 16
// speedup vs baseline: 1.4478x; 1.1033x over previous
#include <cuda_runtime.h>
#include <cstdint>

#define B_ROWS 4096
#define N_LEN  8192
#define M_FFT  4096
#define THREADS 512
#define GRID_CTAS (B_ROWS / 2)
#define WAVE_CTAS 296        // 148 SMs x 2 CTAs/SM

#define MIN_IDX 273           // argmin |f - 40/60|  (f[i] = i*5/2048, exact fp32)
#define MAX_IDX 1707          // argmin |f - 250/60|  (band = [273, 1707) )
#define DF 0.00244140625f     // 10/4096, exact fp32

// smem layout (bytes from dynamic base)
#define ZA_OFF   0
#define ZB_OFF   32768
#define RED_OFF  65536                  // 64-float reduction strip
#define SMEM_TOTAL (RED_OFF + 256)      // 65792

__device__ float g_losses[B_ROWS];
__device__ unsigned int g_ctr = 0;      // last-CTA counter (self-resetting)

// GF(2)-linear swizzle on c64 indices (conflict-free for all stage
// patterns; validated R5-R15, rel_err 0).
__host__ __device__ constexpr int Sc(int i)
{
    return i ^ ((i >> 6) & 1) ^ ((i >> 5) & 0xC) ^ ((i >> 8) & 0xE);
}

// cos(pi*m/32) and sin(pi*m/32) literals, m in [0, 49] (stage<8> twiddles).
__device__ __constant__ const float C64c[50] = {
 1.0f, 0.99518472667219693f, 0.98078528040323044f, 0.95694033573220886f,
 0.92387953251128676f, 0.88192126434835503f, 0.83146961230254524f,
 0.77301045336273696f, 0.70710678118654752f, 0.63439328416364549f,
 0.55557023301960222f, 0.47139673682599764f, 0.38268343236508977f,
 0.29028467725446233f, 0.19509032201612827f, 0.09801714032956060f,
 0.0f, -0.09801714032956060f, -0.19509032201612827f, -0.29028467725446233f,
 -0.38268343236508977f, -0.47139673682599764f, -0.55557023301960222f,
 -0.63439328416364549f, -0.70710678118654752f, -0.77301045336273696f,
 -0.83146961230254524f, -0.88192126434835503f, -0.92387953251128676f,
 -0.95694033573220886f, -0.98078528040323044f, -0.99518472667219693f,
 -1.0f, -0.99518472667219693f, -0.98078528040323044f, -0.95694033573220886f,
 -0.92387953251128676f, -0.88192126434835503f, -0.83146961230254524f,
 -0.77301045336273696f, -0.70710678118654752f, -0.63439328416364549f,
 -0.55557023301960222f, -0.47139673682599764f, -0.38268343236508977f,
 -0.29028467725446233f, -0.19509032201612827f, -0.09801714032956060f,
 0.0f, 0.09801714032956060f };
__device__ __constant__ const float S64c[50] = {
 0.0f, 0.09801714032956060f, 0.19509032201612827f, 0.29028467725446233f,
 0.38268343236508977f, 0.47139673682599764f, 0.55557023301960222f,
 0.63439328416364549f, 0.70710678118654752f, 0.77301045336273696f,
 0.83146961230254524f, 0.88192126434835503f, 0.92387953251128676f,
 0.95694033573220886f, 0.98078528040323044f, 0.99518472667219693f,
 1.0f, 0.99518472667219693f, 0.98078528040323044f, 0.95694033573220886f,
 0.92387953251128676f, 0.88192126434835503f, 0.83146961230254524f,
 0.77301045336273696f, 0.70710678118654752f, 0.63439328416364549f,
 0.55557023301960222f, 0.47139673682599764f, 0.38268343236508977f,
 0.29028467725446233f, 0.19509032201612827f, 0.09801714032956060f,
 0.0f, -0.09801714032956060f, -0.19509032201612827f, -0.29028467725446233f,
 -0.38268343236508977f, -0.47139673682599764f, -0.55557023301960222f,
 -0.63439328416364549f, -0.70710678118654752f, -0.77301045336273696f,
 -0.83146961230254524f, -0.88192126434835503f, -0.92387953251128676f,
 -0.95694033573220886f, -0.98078528040323044f, -0.99518472667219693f,
 -1.0f, -0.99518472667219693f };

#define C64L(m) (C64c[m])
#define S64L(m) (S64c[m])

// ---------- packed f32x2 complex helpers ----------
typedef unsigned long long c64;      // (real, imag) packed as 2 x f32

__device__ __forceinline__ c64 pk(float lo, float hi)
{
    c64 r;
    asm("mov.b64 %0, {%1, %2};" : "=l"(r) : "f"(lo), "f"(hi));
    return r;
}
__device__ __forceinline__ float lof(c64 a)
{
    float f;
    asm("{ .reg .f32 h; mov.b64 {%0, h}, %1; }" : "=f"(f) : "l"(a));
    return f;
}
__device__ __forceinline__ float hif(c64 a)
{
    float f;
    asm("{ .reg .f32 l; mov.b64 {l, %0}, %1; }" : "=f"(f) : "l"(a));
    return f;
}
__device__ __forceinline__ c64 addc(c64 a, c64 b)
{
    c64 r;
    asm("add.rn.f32x2 %0, %1, %2;" : "=l"(r) : "l"(a), "l"(b));
    return r;
}
__device__ __forceinline__ c64 subc(c64 a, c64 b, c64 NEG1)
{
    c64 r;
    asm("fma.rn.f32x2 %0, %1, %2, %3;" : "=l"(r) : "l"(b), "l"(NEG1), "l"(a));
    return r;
}
__device__ __forceinline__ c64 sclc(c64 a, c64 s)
{
    c64 r;
    asm("mul.rn.f32x2 %0, %1, %2;" : "=l"(r) : "l"(a), "l"(s));
    return r;
}
// multiply by -i: (r, i) -> (i, -r)
__device__ __forceinline__ c64 mni(c64 a)
{
    return pk(hif(a), -lof(a));
}
// scalar cmul producing packed result: v * (wr + i*wi)
__device__ __forceinline__ c64 cmulp(c64 v, float wr, float wi)
{
    float ar = lof(v), ai = hif(v);
    return pk(ar * wr - ai * wi, ar * wi + ai * wr);
}
__device__ __forceinline__ void cmul(float ar, float ai, float br, float bi,
                                     float& cr, float& ci)
{
    cr = ar * br - ai * bi;
    ci = ar * bi + ai * br;
}

// 8-point DFT (DIT), natural order, in-place, packed f32x2 arithmetic.
__device__ __forceinline__ void dft8p(c64* x, c64 NEG1, c64 CC)
{
    c64 t0 = addc(x[0], x[4]), t1 = subc(x[0], x[4], NEG1);
    c64 t2 = addc(x[2], x[6]), t3 = subc(x[2], x[6], NEG1);
    c64 E0 = addc(t0, t2),     E2 = subc(t0, t2, NEG1);
    c64 mt3 = mni(t3);
    c64 E1 = addc(t1, mt3),    E3 = subc(t1, mt3, NEG1);
    c64 s0 = addc(x[1], x[5]), s1 = subc(x[1], x[5], NEG1);
    c64 s2 = addc(x[3], x[7]), s3 = subc(x[3], x[7], NEG1);
    c64 O0 = addc(s0, s2),     O2 = subc(s0, s2, NEG1);
    c64 ms3 = mni(s3);
    c64 O1 = addc(s1, ms3),    O3 = subc(s1, ms3, NEG1);
    c64 P1 = sclc(addc(O1, mni(O1)), CC);
    c64 P2 = mni(O2);
    c64 P3 = sclc(subc(mni(O3), O3, NEG1), CC);
    x[0] = addc(E0, O0); x[4] = subc(E0, O0, NEG1);
    x[1] = addc(E1, P1); x[5] = subc(E1, P1, NEG1);
    x[2] = addc(E2, P2); x[6] = subc(E2, P2, NEG1);
    x[3] = addc(E3, P3); x[7] = subc(E3, P3, NEG1);
}

// Twiddle powers w^1..w^7 via depth-3 tree (shared by both rows).
__device__ __forceinline__ void wpowers(float w1r, float w1i, float* wr, float* wi)
{
    wr[1] = w1r; wi[1] = w1i;
    cmul(w1r, w1i, w1r, w1i, wr[2], wi[2]);
    cmul(wr[2], wi[2], w1r, w1i, wr[3], wi[3]);
    cmul(wr[2], wi[2], wr[2], wi[2], wr[4], wi[4]);
    cmul(wr[2], wi[2], wr[3], wi[3], wr[5], wi[5]);
    cmul(wr[3], wi[3], wr[3], wi[3], wr[6], wi[6]);
    cmul(wr[3], wi[3], wr[4], wi[4], wr[7], wi[7]);
}

// Stage<8> specialized per warp-uniform p (compile-time twiddles).
template <int P>
__device__ __forceinline__ void stage8_fixed(c64* zA, c64* zB, int tid,
                                             c64 NEG1, c64 CC)
{
    const int g    = tid & 63;
    const int base = g * 64 + P;
    const int q0   = Sc(base);

    c64 vA[8], vB[8];
    #pragma unroll
    for (int k = 0; k < 8; ++k) {
        int q = q0 ^ Sc(k * 8);
        vA[k] = zA[q];
        vB[k] = zB[q];
    }

    c64 xA[8], xB[8];
    xA[0] = vA[0]; xB[0] = vB[0];
    #pragma unroll
    for (int k = 1; k < 8; ++k) {
        if (P == 0) {
            xA[k] = vA[k];
            xB[k] = vB[k];
        } else {
            const float wr =  C64L(P * k);
            const float wi = -S64L(P * k);
            xA[k] = cmulp(vA[k], wr, wi);
            xB[k] = cmulp(vB[k], wr, wi);
        }
    }
    dft8p(xA, NEG1, CC);
    dft8p(xB, NEG1, CC);
    #pragma unroll
    for (int k = 0; k < 8; ++k) {
        int q = q0 ^ Sc(k * 8);
        zA[q] = xA[k];
        zB[q] = xB[k];
    }
}

// Stage<64>: base twiddle computed per-thread via sincospif (MUFU is idle;
// replaces the smem table lookup).
__device__ __forceinline__ void stage64_2(c64* zA, c64* zB, int tid,
                                          c64 NEG1, c64 CC)
{
    const int p = tid >> 3, g = tid & 7;
    const int base = g * 512 + p;
    const int q0   = Sc(base);

    c64 vA[8], vB[8];
    #pragma unroll
    for (int k = 0; k < 8; ++k) {
        int q = q0 ^ Sc(k * 64);
        vA[k] = zA[q];
        vB[k] = zB[q];
    }

    // w1 = exp(-2*pi*i*p/512); computed while the 16 LDS above are in flight.
    float w1s, w1c;
    sincospif(-(float)p * (1.0f / 256.0f), &w1s, &w1c);
    float wr[8], wi[8];
    wpowers(w1c, w1s, wr, wi);

    c64 xA[8], xB[8];
    xA[0] = vA[0]; xB[0] = vB[0];
    #pragma unroll
    for (int k = 1; k < 8; ++k) {
        xA[k] = cmulp(vA[k], wr[k], wi[k]);
        xB[k] = cmulp(vB[k], wr[k], wi[k]);
    }
    dft8p(xA, NEG1, CC);
    dft8p(xB, NEG1, CC);
    #pragma unroll
    for (int k = 0; k < 8; ++k) {
        int q = q0 ^ Sc(k * 64);
        zA[q] = xA[k];
        zB[q] = xB[k];
    }
}

__global__ void __launch_bounds__(THREADS, 2) snr_fft_kernel(
    const float* __restrict__ outputs,
    const float* __restrict__ targets,
    float* __restrict__ d_out)
{
    extern __shared__ float smem_raw[];
    char* sb = reinterpret_cast<char*>(smem_raw);
    c64*   zA  = reinterpret_cast<c64*>(sb + ZA_OFF);    // 4096 c64
    c64*   zB  = reinterpret_cast<c64*>(sb + ZB_OFF);    // 4096 c64
    float* red = reinterpret_cast<float*>(sb + RED_OFF); // 64 floats

    const int tid = threadIdx.x;
    const int rowA = 2 * blockIdx.x;

    const c64 NEG1 = 0xBF800000BF800000ULL;              // (-1.0f, -1.0f)
    const c64 CC   = pk(0.70710678118654752f, 0.70710678118654752f);

    // Hoist targets (used late; pull latency to the front).
    const float tgtA = targets[rowA];
    const float tgtB = targets[rowA + 1];

    // Fused coalesced load + stage 1 for BOTH rows (16 LDG.64, MLP=16).
    {
        const c64* xrA = reinterpret_cast<const c64*>(outputs) + (size_t)rowA * M_FFT;
        const c64* xrB = xrA + M_FFT;
        c64 a[8], b[8];
        #pragma unroll
        for (int k = 0; k < 8; ++k) {
            a[k] = xrA[tid + (k << 9)];
            b[k] = xrB[tid + (k << 9)];
        }

        // L2 prefetch for the CTA one wave ahead (64KB = 512 x 128B lines).
        // Issued after demand loads; single wave depth (two-wave regressed).
        {
            int pf = blockIdx.x + WAVE_CTAS;
            if (pf < GRID_CTAS) {
                const char* np = reinterpret_cast<const char*>(
                    outputs + (size_t)(2 * pf) * N_LEN) + tid * 128;
                asm volatile("prefetch.global.L2 [%0];" :: "l"(np));
            }
        }

        dft8p(a, NEG1, CC);
        dft8p(b, NEG1, CC);
        const int t8 = ((tid & 7) << 6) | (((tid >> 3) & 7) << 3) | (tid >> 6);
        const int q0 = Sc(t8 << 3);
        #pragma unroll
        for (int k = 0; k < 8; ++k) {      // Sc(k) = k for k < 8
            zA[q0 ^ k] = a[k];
            zB[q0 ^ k] = b[k];
        }
    }
    __syncthreads();     // stage-1 data published

    // Stage <8>: warp-uniform p = tid>>6 -> compile-time twiddles.
    switch (tid >> 6) {
        case 0: stage8_fixed<0>(zA, zB, tid, NEG1, CC); break;
        case 1: stage8_fixed<1>(zA, zB, tid, NEG1, CC); break;
        case 2: stage8_fixed<2>(zA, zB, tid, NEG1, CC); break;
        case 3: stage8_fixed<3>(zA, zB, tid, NEG1, CC); break;
        case 4: stage8_fixed<4>(zA, zB, tid, NEG1, CC); break;
        case 5: stage8_fixed<5>(zA, zB, tid, NEG1, CC); break;
        case 6: stage8_fixed<6>(zA, zB, tid, NEG1, CC); break;
        default: stage8_fixed<7>(zA, zB, tid, NEG1, CC); break;
    }
    __syncthreads();

    stage64_2(zA, zB, tid, NEG1, CC);
    __syncthreads();

    // Epilogue base twiddle: Wt = exp(-i*pi*tid/4096) (also feeds stage-512).
    float Wts, Wtc;
    sincospif(-(float)tid * (1.0f / 4096.0f), &Wts, &Wtc);

    // Stage L=512: load BOTH rows first, then compute.
    // w1 = exp(-2*pi*i*tid/4096) = Wt^2.
    c64 bA[4], bB[4];
    {
        const int q0 = Sc(tid);
        c64 vA[8], vB[8];
        #pragma unroll
        for (int k = 0; k < 8; ++k) {
            int q = q0 ^ Sc(k * 512);
            vA[k] = zA[q];
            vB[k] = zB[q];
        }

        float w1r, w1i;
        cmul(Wtc, Wts, Wtc, Wts, w1r, w1i);      // Wt^2
        float wr[8], wi[8];
        wpowers(w1r, w1i, wr, wi);

        c64 xA[8], xB[8];
        xA[0] = vA[0]; xB[0] = vB[0];
        #pragma unroll
        for (int k = 1; k < 8; ++k) {
            xA[k] = cmulp(vA[k], wr[k], wi[k]);
            xB[k] = cmulp(vB[k], wr[k], wi[k]);
        }
        dft8p(xA, NEG1, CC);
        dft8p(xB, NEG1, CC);

        // Publish only the index range the epilogue reads: [272, 3824].
        #pragma unroll
        for (int k = 0; k < 8; ++k) {
            bool need = (k == 0) ? (tid >= 272)
                      : (k == 7) ? (tid <= 240)
                      : true;
            if (need) {
                int q = q0 ^ Sc(k * 512);
                zA[q] = xA[k];
                zB[q] = xB[k];
            }
        }
        #pragma unroll
        for (int k = 0; k < 4; ++k) { bA[k] = xA[k]; bB[k] = xB[k]; }
    }
    __syncthreads();     // final Z published for both rows

    // Weight-free band sums over k in [273, 1706] for both rows.
    // Unpack twiddle folded: W(tid + 512c) = Wt * exp(-i*pi*c/8).
    const float ecr[4] = { 1.0f, 0.92387953251128675613f,
                           0.70710678118654752440f, 0.38268343236508977173f };
    const float eci[4] = { 0.0f, -0.38268343236508977173f,
                          -0.70710678118654752440f, -0.92387953251128675613f };
    float bandA0 = 0.0f, bandA1 = 0.0f, bandB0 = 0.0f, bandB1 = 0.0f;
    #pragma unroll
    for (int c = 0; c < 4; ++c) {
        int k = tid + (c << 9);
        bool valid = (c == 1) || (c == 2) ||
                     (c == 0 ? (tid >= MIN_IDX) : (k <= MAX_IDX - 1));
        if (valid) {
            float Wr, Wi;
            if (c == 0) { Wr = Wtc; Wi = Wts; }
            else        { cmul(Wtc, Wts, ecr[c], eci[c], Wr, Wi); }
            int q2 = Sc(M_FFT - k);
            {   // row A
                c64 Z2p = zA[q2];
                float Z2r = lof(Z2p), Z2i = hif(Z2p);
                float xrc = lof(bA[c]), xic = hif(bA[c]);
                float Er = 0.5f * (xrc + Z2r);
                float Ei = 0.5f * (xic - Z2i);
                float Or = 0.5f * (xic + Z2i);
                float Oi = 0.5f * (Z2r - xrc);
                float Xr = Er + Wr * Or - Wi * Oi;
                float Xi = Ei + Wr * Oi + Wi * Or;
                float pw = (Xr * Xr + Xi * Xi) * (1.0f / (float)N_LEN);
                if (c & 1) bandA1 += pw; else bandA0 += pw;
            }
            {   // row B
                c64 Z2p = zB[q2];
                float Z2r = lof(Z2p), Z2i = hif(Z2p);
                float xrc = lof(bB[c]), xic = hif(bB[c]);
                float Er = 0.5f * (xrc + Z2r);
                float Ei = 0.5f * (xic - Z2i);
                float Or = 0.5f * (xic + Z2i);
                float Oi = 0.5f * (Z2r - xrc);
                float Xr = Er + Wr * Or - Wi * Oi;
                float Xi = Ei + Wr * Oi + Wi * Or;
                float pw = (Xr * Xr + Xi * Xi) * (1.0f / (float)N_LEN);
                if (c & 1) bandB1 += pw; else bandB0 += pw;
            }
        }
    }
    float bandA = bandA0 + bandA1;
    float bandB = bandB0 + bandB1;

    // Special bins: threads 0..5 do row A, threads 8..13 do row B.
    float spec_sig = 0.0f, spec_corr = 0.0f;
    bool isSpec = (tid < 6) || (tid >= 8 && tid < 14);
    if (isSpec) {
        bool isB = tid >= 8;
        int s = isB ? tid - 8 : tid;
        const int   joff[6] = { -1, 0, 1, -1, 0, 1 };
        const float uw[6]   = { 0.5f, 1.0f, 0.5f, 0.0f, 1.0f, 0.0f };
        const float mw[6]   = { 0.5f, 1.0f, 0.5f, 1.0f, 1.0f, 1.0f };
        const float tgt = isB ? tgtB : tgtA;
        int ib = (int)floorf(tgt / DF) - 1;
        if (ib < 0) ib = 0;
        if (ib > M_FFT - 3) ib = M_FFT - 3;
        int r = ib;
        float best = fabsf((float)ib * DF - tgt);
        #pragma unroll
        for (int i = 1; i <= 3; ++i) {
            float d = fabsf((float)(ib + i) * DF - tgt);
            if (d < best) { best = d; r = ib + i; }
        }
        int j = (s < 3 ? r : 2 * r) + joff[s];
        const c64* zp = isB ? zB : zA;
        c64 Z1p = zp[Sc(j)];
        c64 Z2p = zp[Sc(M_FFT - j)];
        float Z1r = lof(Z1p), Z1i = hif(Z1p);
        float Z2r = lof(Z2p), Z2i = hif(Z2p);
        float Er = 0.5f * (Z1r + Z2r);
        float Ei = 0.5f * (Z1i - Z2i);
        float Or = 0.5f * (Z1i + Z2i);
        float Oi = 0.5f * (Z2r - Z1r);
        float Ws, Wc;
        sincospif(-(float)j * (1.0f / 4096.0f), &Ws, &Wc);
        float Xr = Er + Wc * Or - Ws * Oi;
        float Xi = Ei + Wc * Oi + Ws * Or;
        float P = (Xr * Xr + Xi * Xi) * (1.0f / (float)N_LEN);
        spec_sig  = uw[s] * P;
        spec_corr = (j >= MIN_IDX && j < MAX_IDX) ? mw[s] * P : 0.0f;
    }

    // Band reductions (both rows) within warps.
    #pragma unroll
    for (int o = 16; o > 0; o >>= 1) {
        bandA += __shfl_down_sync(0xffffffffu, bandA, o);
        bandB += __shfl_down_sync(0xffffffffu, bandB, o);
    }
    const int wid = tid >> 5, lane = tid & 31;
    __syncthreads();     // all z reads complete before red reuse barrier
    if (lane == 0) { red[wid] = bandA; red[16 + wid] = bandB; }
    if (isSpec) {
        bool isB = tid >= 8;
        int s = isB ? tid - 8 : tid;
        int off = isB ? 44 : 32;
        red[off + s]     = spec_sig;
        red[off + 6 + s] = spec_corr;
    }
    __syncthreads();

    __shared__ bool is_last;
    if (tid < 2) {
        int boff = tid ? 16 : 0;
        int soff = tid ? 44 : 32;
        float Bt = 0.0f;
        #pragma unroll
        for (int i = 0; i < 16; ++i) Bt += red[boff + i];
        float Sg = 0.0f, Cr = 0.0f;
        #pragma unroll
        for (int i = 0; i < 6; ++i) { Sg += red[soff + i]; Cr += red[soff + 6 + i]; }
        g_losses[rowA + tid] = -10.0f * log10f(Sg / ((Bt - Cr) + 1.0f));
        __threadfence();
    }
    __syncthreads();
    if (tid == 0) {
        unsigned int old = atomicAdd(&g_ctr, 1u);
        is_last = (old == (unsigned int)(GRID_CTAS - 1));
    }
    __syncthreads();

    // Last CTA computes the mean (fixed-order, deterministic), resets ctr.
    if (is_last) {
        float s = 0.0f;
        for (int i = tid; i < B_ROWS; i += THREADS) s += g_losses[i];
        #pragma unroll
        for (int o = 16; o > 0; o >>= 1) s += __shfl_down_sync(0xffffffffu, s, o);
        __syncthreads();
        if (lane == 0) red[wid] = s;
        __syncthreads();
        if (tid == 0) {
            float t = 0.0f;
            #pragma unroll
            for (int i = 0; i < 16; ++i) t += red[i];
            d_out[0] = t * (1.0f / (float)B_ROWS);
            g_ctr = 0;
        }
    }
}

extern "C" void kernel_launch(void* const* d_in, const int* in_sizes, int n_in,
                              void* d_out, int out_size)
{
    const float* outputs = (const float*)d_in[0];   // [4096, 8192] f32
    const float* targets = (const float*)d_in[1];   // [4096, 1]    f32
    (void)in_sizes; (void)n_in; (void)out_size;

    cudaFuncSetAttribute(snr_fft_kernel,
                         cudaFuncAttributeMaxDynamicSharedMemorySize, SMEM_TOTAL);

    snr_fft_kernel<<<GRID_CTAS, THREADS, SMEM_TOTAL>>>(outputs, targets, (float*)d_out);
}